// round 16
// baseline (speedup 1.0000x reference)
#include <cuda_runtime.h>
#include <cuda_fp16.h>
#include <cstdint>
#include <cstddef>

// B=4,H=16,S=2048,D=64 fp32.  out = [ctx (64*2048*64)] ++ [attn (64*2048*2048)]
// score = QK^T/8 ; attn = relu(score) ; ctx = attn @ V
// fp16 mma.sync 1-pass gemms; pre-converted fp16 K/V scratch; double-buffered
// cp.async. gemm1 split into two 64-col halves (C1=32 regs live) -> 2 CTAs/SM.
#define S_LEN 2048
#define HDIM  64
#define BLK   128
#define NT    256
#define NTILES (S_LEN / BLK)
#define NBH   64
#define CTX_ELEMS 8388608LL

#define OFF_Q  0                // 16KB fp16 Q tile
#define BUF0   16384            // two 32KB staging buffers (KH|VH)
#define BUFSTR 32768
#define SMEM_BYTES 81920        // 80KB -> 2 CTAs/SM (160KB)
#define RED_STRIDE 72

// pre-converted, pre-swizzled fp16 K/V hi tiles: [bh][tile][KH|VH each 16KB]
__device__ __align__(16) unsigned char SPLIT_KV[(size_t)NBH * NTILES * BUFSTR];

__device__ __forceinline__ uint32_t cvta_smem(const void* p) {
    uint32_t a;
    asm("{ .reg .u64 t; cvta.to.shared.u64 t, %1; cvt.u32.u64 %0, t; }" : "=r"(a) : "l"(p));
    return a;
}
__device__ __forceinline__ void ldsm4(uint32_t r[4], uint32_t a) {
    asm volatile("ldmatrix.sync.aligned.m8n8.x4.shared.b16 {%0,%1,%2,%3}, [%4];"
                 : "=r"(r[0]), "=r"(r[1]), "=r"(r[2]), "=r"(r[3]) : "r"(a));
}
__device__ __forceinline__ void ldsm4t(uint32_t r[4], uint32_t a) {
    asm volatile("ldmatrix.sync.aligned.m8n8.x4.trans.shared.b16 {%0,%1,%2,%3}, [%4];"
                 : "=r"(r[0]), "=r"(r[1]), "=r"(r[2]), "=r"(r[3]) : "r"(a));
}
__device__ __forceinline__ void mmah(float c[4], const uint32_t a[4],
                                     uint32_t b0, uint32_t b1) {
    asm volatile("mma.sync.aligned.m16n8k16.row.col.f32.f16.f16.f32 "
                 "{%0,%1,%2,%3}, {%4,%5,%6,%7}, {%8,%9}, {%0,%1,%2,%3};"
                 : "+f"(c[0]), "+f"(c[1]), "+f"(c[2]), "+f"(c[3])
                 : "r"(a[0]), "r"(a[1]), "r"(a[2]), "r"(a[3]), "r"(b0), "r"(b1));
}
__device__ __forceinline__ uint32_t packh(float lo, float hi) {
    uint32_t d;
    asm("cvt.rn.f16x2.f32 %0, %1, %2;" : "=r"(d) : "f"(hi), "f"(lo));
    return d;
}
__device__ __forceinline__ int swz_byte(int row, int c4f) {
    int chunk = c4f >> 1, within = (c4f & 1) * 8;
    return row * 128 + ((chunk ^ (row & 7)) << 4) + within;
}
__device__ __forceinline__ uint2 cvt4h(float4 v) {
    return make_uint2(packh(v.x, v.y), packh(v.z, v.w));
}
__device__ __forceinline__ void cp16(uint32_t saddr, const void* g) {
    asm volatile("cp.async.cg.shared.global [%0], [%1], 16;" :: "r"(saddr), "l"(g) : "memory");
}
#define CP_COMMIT() asm volatile("cp.async.commit_group;" ::: "memory")
#define CP_WAIT0()  asm volatile("cp.async.wait_group 0;" ::: "memory")

// ============ preprocess: convert K/V hi to swizzled fp16 scratch ============
__global__ __launch_bounds__(NT)
void conv_kv_kernel(const float* __restrict__ K, const float* __restrict__ V) {
    const int kt = blockIdx.x, bh = blockIdx.y, tid = threadIdx.x;
    const float4* Kg4 = (const float4*)(K + ((size_t)bh * S_LEN + kt * BLK) * HDIM);
    const float4* Vg4 = (const float4*)(V + ((size_t)bh * S_LEN + kt * BLK) * HDIM);
    unsigned char* out = SPLIT_KV + (size_t)(bh * NTILES + kt) * BUFSTR;
    #pragma unroll
    for (int it = 0; it < 8; it++) {
        int i = tid + it * NT;
        int byte = swz_byte(i >> 4, i & 15);
        *(uint2*)(out + byte)         = cvt4h(Kg4[i]);
        *(uint2*)(out + 16384 + byte) = cvt4h(Vg4[i]);
    }
}

// ============ main fused kernel ============
__global__ __launch_bounds__(NT, 2)
void relu_attn_half_kernel(const float* __restrict__ Q,
                           float* __restrict__ ctx,
                           float* __restrict__ attn) {
    extern __shared__ char smc[];
    const uint32_t sb = cvta_smem(smc);

    const int tid  = threadIdx.x;
    const int lane = tid & 31;
    const int w    = tid >> 5;
    const int wq   = w >> 1;        // 0..3: q rows [wq*32, wq*32+32)
    const int wn   = w & 1;         // 0..1: gemm1 cols [wn*64, wn*64+64)
    const int bh   = blockIdx.y;
    const int q0   = blockIdx.x * BLK;

    const unsigned char* kvb = SPLIT_KV + (size_t)bh * NTILES * BUFSTR;
    float* attng = attn + ((size_t)bh * S_LEN + q0) * S_LEN;
    float* ctxg  = ctx  + ((size_t)bh * S_LEN + q0) * HDIM;

    // ---- stage tile 0 + convert Q (scaled by 1/8, fp16) ----
    {
        #pragma unroll
        for (int it = 0; it < 8; it++) {
            int off = (tid + it * NT) * 16;
            cp16(sb + BUF0 + off, kvb + off);
        }
        CP_COMMIT();
        const float4* Qg4 = (const float4*)(Q + ((size_t)bh * S_LEN + q0) * HDIM);
        #pragma unroll
        for (int it = 0; it < 8; it++) {
            int i = tid + it * NT;
            int byte = swz_byte(i >> 4, i & 15);
            float4 v = Qg4[i];
            v.x *= 0.125f; v.y *= 0.125f; v.z *= 0.125f; v.w *= 0.125f;
            *(uint2*)(smc + OFF_Q + byte) = cvt4h(v);
        }
        CP_WAIT0();
    }
    __syncthreads();

    const int aRowL     = lane & 15;
    const int aChunkOff = lane >> 4;
    const int bRowOff   = (lane & 7) + ((lane >> 4) << 3);
    const int bChunkOff = (lane >> 3) & 1;
    const int vRowOff   = (lane & 7) + (((lane >> 3) & 1) << 3);
    const int vChunkOff = lane >> 4;

    float C2[2][8][4];
    #pragma unroll
    for (int g = 0; g < 2; g++)
        #pragma unroll
        for (int t = 0; t < 8; t++)
            #pragma unroll
            for (int k = 0; k < 4; k++) C2[g][t][k] = 0.0f;

    for (int kt = 0; kt < NTILES; kt++) {
        const uint32_t cbuf = sb + BUF0 + (uint32_t)(kt & 1) * BUFSTR;

        // prefetch next tile into the other buffer (hidden behind compute)
        if (kt + 1 < NTILES) {
            uint32_t nbuf = sb + BUF0 + (uint32_t)((kt + 1) & 1) * BUFSTR;
            const unsigned char* src = kvb + (size_t)(kt + 1) * BUFSTR;
            #pragma unroll
            for (int it = 0; it < 8; it++) {
                int off = (tid + it * NT) * 16;
                cp16(nbuf + off, src + off);
            }
        }
        CP_COMMIT();

        const uint32_t vbase = cbuf + 16384;

        // ---- two 64-col halves: gemm1(half) -> epilogue+gemm2(half) ----
        #pragma unroll
        for (int h = 0; h < 2; h++) {
            float C1[2][4][4];
            #pragma unroll
            for (int g = 0; g < 2; g++)
                #pragma unroll
                for (int t = 0; t < 4; t++)
                    #pragma unroll
                    for (int k = 0; k < 4; k++) C1[g][t][k] = 0.0f;

            #pragma unroll
            for (int kc = 0; kc < 4; kc++) {
                uint32_t aH[2][4];
                #pragma unroll
                for (int g = 0; g < 2; g++) {
                    int arow = wq * 32 + g * 16 + aRowL;
                    int ch = kc * 2 + aChunkOff;
                    ldsm4(aH[g], sb + OFF_Q + arow * 128
                                 + (uint32_t)((ch ^ (arow & 7)) << 4));
                }
                #pragma unroll
                for (int nt2l = 0; nt2l < 2; nt2l++) {
                    int nt2 = h * 2 + nt2l;
                    int brow = wn * 64 + nt2 * 16 + bRowOff;
                    int bch  = kc * 2 + bChunkOff;
                    uint32_t bHf[4];
                    ldsm4(bHf, cbuf + brow * 128
                               + (uint32_t)((bch ^ (brow & 7)) << 4));
                    #pragma unroll
                    for (int g = 0; g < 2; g++) {
                        mmah(C1[g][2 * nt2l],     aH[g], bHf[0], bHf[1]);
                        mmah(C1[g][2 * nt2l + 1], aH[g], bHf[2], bHf[3]);
                    }
                }
            }

            // epilogue + gemm2 for this half's two 16-k chunks
            #pragma unroll
            for (int nt2l = 0; nt2l < 2; nt2l++) {
                int nt2 = h * 2 + nt2l;
                uint32_t ah[2][4];
                #pragma unroll
                for (int g = 0; g < 2; g++) {
                    float* ag = attng
                        + (size_t)(wq * 32 + g * 16 + (lane >> 2)) * S_LEN
                        + (size_t)kt * BLK + wn * 64 + nt2 * 16 + (lane & 3) * 2;
                    #pragma unroll
                    for (int sub = 0; sub < 2; sub++) {
                        float* c = C1[g][2 * nt2l + sub];
                        float p0 = fmaxf(c[0], 0.0f);
                        float p1 = fmaxf(c[1], 0.0f);
                        float p2 = fmaxf(c[2], 0.0f);
                        float p3 = fmaxf(c[3], 0.0f);
                        __stcs((float2*)(ag + sub * 8),             make_float2(p0, p1));
                        __stcs((float2*)(ag + sub * 8 + 8 * S_LEN), make_float2(p2, p3));
                        ah[g][2 * sub]     = packh(p0, p1);
                        ah[g][2 * sub + 1] = packh(p2, p3);
                    }
                }
                int vrow = wn * 64 + nt2 * 16 + vRowOff;
                #pragma unroll
                for (int ntV = 0; ntV < 4; ntV++) {
                    int vch = ntV * 2 + vChunkOff;
                    uint32_t vf[4];
                    ldsm4t(vf, vbase + vrow * 128
                               + (uint32_t)((vch ^ (vrow & 7)) << 4));
                    #pragma unroll
                    for (int g = 0; g < 2; g++) {
                        mmah(C2[g][2 * ntV],     ah[g], vf[0], vf[1]);
                        mmah(C2[g][2 * ntV + 1], ah[g], vf[2], vf[3]);
                    }
                }
            }
        }

        CP_WAIT0();
        __syncthreads();
    }

    // ---- split-k reduction of C2 across wn pairs, then write ctx ----
    float* red = (float*)smc;   // overlays Q + tile buffers (done with them)
    if (wn == 1) {
        #pragma unroll
        for (int g = 0; g < 2; g++) {
            int r = wq * 32 + g * 16 + (lane >> 2);
            #pragma unroll
            for (int t = 0; t < 8; t++) {
                int col = (t >> 1) * 16 + (t & 1) * 8 + (lane & 3) * 2;
                *(float2*)&red[(size_t)r * RED_STRIDE + col] =
                    make_float2(C2[g][t][0], C2[g][t][1]);
                *(float2*)&red[(size_t)(r + 8) * RED_STRIDE + col] =
                    make_float2(C2[g][t][2], C2[g][t][3]);
            }
        }
    }
    __syncthreads();
    if (wn == 0) {
        #pragma unroll
        for (int g = 0; g < 2; g++) {
            int r = wq * 32 + g * 16 + (lane >> 2);
            #pragma unroll
            for (int t = 0; t < 8; t++) {
                int col = (t >> 1) * 16 + (t & 1) * 8 + (lane & 3) * 2;
                float2 p0 = *(float2*)&red[(size_t)r * RED_STRIDE + col];
                float2 p1 = *(float2*)&red[(size_t)(r + 8) * RED_STRIDE + col];
                *(float2*)&ctxg[(size_t)r * HDIM + col] =
                    make_float2(C2[g][t][0] + p0.x, C2[g][t][1] + p0.y);
                *(float2*)&ctxg[(size_t)(r + 8) * HDIM + col] =
                    make_float2(C2[g][t][2] + p1.x, C2[g][t][3] + p1.y);
            }
        }
    }
}

extern "C" void kernel_launch(void* const* d_in, const int* in_sizes, int n_in,
                              void* d_out, int out_size) {
    const float* Q = (const float*)d_in[0];
    const float* K = (const float*)d_in[1];
    const float* V = (const float*)d_in[2];
    float* ctx  = (float*)d_out;
    float* attn = (float*)d_out + CTX_ELEMS;

    dim3 pg(NTILES, NBH);
    conv_kv_kernel<<<pg, NT>>>(K, V);

    cudaFuncSetAttribute(relu_attn_half_kernel,
                         cudaFuncAttributeMaxDynamicSharedMemorySize, SMEM_BYTES);
    dim3 grid(S_LEN / BLK, NBH);
    relu_attn_half_kernel<<<grid, NT, SMEM_BYTES>>>(Q, ctx, attn);
}

// round 17
// speedup vs baseline: 1.3348x; 1.3348x over previous
#include <cuda_runtime.h>
#include <cuda_fp16.h>
#include <cstdint>
#include <cstddef>

// B=4,H=16,S=2048,D=64 fp32.  out = [ctx (64*2048*64)] ++ [attn (64*2048*2048)]
// score = QK^T/8 ; attn = relu(score) ; ctx = attn @ V
// fp16 mma.sync 1-pass gemms; pre-converted fp16 K/V scratch; 4-stage cp.async
// pipeline with one barrier per 2 tiles; hoisted Q fragments (R13 body).
#define S_LEN 2048
#define HDIM  64
#define BLK   128
#define NT    256
#define NTILES (S_LEN / BLK)
#define NPAIRS (NTILES / 2)
#define NBH   64
#define CTX_ELEMS 8388608LL

#define OFF_QH 0
#define BUF0   16384
#define BUFSTR 32768            // per-tile buffer: KH at +0, VH at +16384
#define SMEM_BYTES (16384 + 4 * 32768)   // 147456
#define RED_STRIDE 72

// pre-converted, pre-swizzled fp16 K/V hi tiles: [bh][tile][KH|VH each 16KB]
__device__ __align__(16) unsigned char SPLIT_KV[(size_t)NBH * NTILES * BUFSTR];

__device__ __forceinline__ uint32_t cvta_smem(const void* p) {
    uint32_t a;
    asm("{ .reg .u64 t; cvta.to.shared.u64 t, %1; cvt.u32.u64 %0, t; }" : "=r"(a) : "l"(p));
    return a;
}
__device__ __forceinline__ void ldsm4(uint32_t r[4], uint32_t a) {
    asm volatile("ldmatrix.sync.aligned.m8n8.x4.shared.b16 {%0,%1,%2,%3}, [%4];"
                 : "=r"(r[0]), "=r"(r[1]), "=r"(r[2]), "=r"(r[3]) : "r"(a));
}
__device__ __forceinline__ void ldsm4t(uint32_t r[4], uint32_t a) {
    asm volatile("ldmatrix.sync.aligned.m8n8.x4.trans.shared.b16 {%0,%1,%2,%3}, [%4];"
                 : "=r"(r[0]), "=r"(r[1]), "=r"(r[2]), "=r"(r[3]) : "r"(a));
}
__device__ __forceinline__ void mmah(float c[4], const uint32_t a[4],
                                     uint32_t b0, uint32_t b1) {
    asm volatile("mma.sync.aligned.m16n8k16.row.col.f32.f16.f16.f32 "
                 "{%0,%1,%2,%3}, {%4,%5,%6,%7}, {%8,%9}, {%0,%1,%2,%3};"
                 : "+f"(c[0]), "+f"(c[1]), "+f"(c[2]), "+f"(c[3])
                 : "r"(a[0]), "r"(a[1]), "r"(a[2]), "r"(a[3]), "r"(b0), "r"(b1));
}
__device__ __forceinline__ uint32_t packh(float lo, float hi) {
    uint32_t d;
    asm("cvt.rn.f16x2.f32 %0, %1, %2;" : "=r"(d) : "f"(hi), "f"(lo));
    return d;
}
__device__ __forceinline__ int swz_byte(int row, int c4f) {
    int chunk = c4f >> 1, within = (c4f & 1) * 8;
    return row * 128 + ((chunk ^ (row & 7)) << 4) + within;
}
__device__ __forceinline__ uint2 cvt4h(float4 v) {
    return make_uint2(packh(v.x, v.y), packh(v.z, v.w));
}
__device__ __forceinline__ void cp16(uint32_t saddr, const void* g) {
    asm volatile("cp.async.cg.shared.global [%0], [%1], 16;" :: "r"(saddr), "l"(g) : "memory");
}
#define CP_COMMIT() asm volatile("cp.async.commit_group;" ::: "memory")
#define CP_WAIT0()  asm volatile("cp.async.wait_group 0;" ::: "memory")

// ============ preprocess: convert K/V hi to swizzled fp16 scratch ============
__global__ __launch_bounds__(NT)
void conv_kv_kernel(const float* __restrict__ K, const float* __restrict__ V) {
    const int kt = blockIdx.x, bh = blockIdx.y, tid = threadIdx.x;
    const float4* Kg4 = (const float4*)(K + ((size_t)bh * S_LEN + kt * BLK) * HDIM);
    const float4* Vg4 = (const float4*)(V + ((size_t)bh * S_LEN + kt * BLK) * HDIM);
    unsigned char* out = SPLIT_KV + (size_t)(bh * NTILES + kt) * BUFSTR;
    #pragma unroll
    for (int it = 0; it < 8; it++) {
        int i = tid + it * NT;
        int byte = swz_byte(i >> 4, i & 15);
        *(uint2*)(out + byte)         = cvt4h(Kg4[i]);
        *(uint2*)(out + 16384 + byte) = cvt4h(Vg4[i]);
    }
}

// ============ main fused kernel ============
__global__ __launch_bounds__(NT, 1)
void relu_attn_pipe4_kernel(const float* __restrict__ Q,
                            float* __restrict__ ctx,
                            float* __restrict__ attn) {
    extern __shared__ char smc[];
    const uint32_t sb = cvta_smem(smc);

    const int tid  = threadIdx.x;
    const int lane = tid & 31;
    const int w    = tid >> 5;
    const int wq   = w >> 1;        // 0..3: q rows [wq*32, wq*32+32)
    const int wn   = w & 1;         // 0..1: gemm1 cols [wn*64, wn*64+64)
    const int bh   = blockIdx.y;
    const int q0   = blockIdx.x * BLK;

    const unsigned char* kvb = SPLIT_KV + (size_t)bh * NTILES * BUFSTR;
    float* attng = attn + ((size_t)bh * S_LEN + q0) * S_LEN;
    float* ctxg  = ctx  + ((size_t)bh * S_LEN + q0) * HDIM;

    // ---- prologue: prefetch tiles 0,1 + convert Q (scaled 1/8) + hoist A ----
    {
        #pragma unroll
        for (int t = 0; t < 2; t++) {
            const unsigned char* src = kvb + (size_t)t * BUFSTR;
            uint32_t dst = sb + BUF0 + (uint32_t)t * BUFSTR;
            #pragma unroll
            for (int it = 0; it < 8; it++) {
                int off = (tid + it * NT) * 16;
                cp16(dst + off, src + off);
            }
            CP_COMMIT();
        }
        const float4* Qg4 = (const float4*)(Q + ((size_t)bh * S_LEN + q0) * HDIM);
        #pragma unroll
        for (int it = 0; it < 8; it++) {
            int i = tid + it * NT;
            int byte = swz_byte(i >> 4, i & 15);
            float4 v = Qg4[i];
            v.x *= 0.125f; v.y *= 0.125f; v.z *= 0.125f; v.w *= 0.125f;
            *(uint2*)(smc + OFF_QH + byte) = cvt4h(v);
        }
    }
    __syncthreads();   // Q visible for the hoist

    const int aRowL     = lane & 15;
    const int aChunkOff = lane >> 4;
    const int bRowOff   = (lane & 7) + ((lane >> 4) << 3);
    const int bChunkOff = (lane >> 3) & 1;
    const int vRowOff   = (lane & 7) + (((lane >> 3) & 1) << 3);
    const int vChunkOff = lane >> 4;

    uint32_t aH[4][2][4];   // hoisted Q fragments
    #pragma unroll
    for (int kc = 0; kc < 4; kc++)
        #pragma unroll
        for (int g = 0; g < 2; g++) {
            int arow = wq * 32 + g * 16 + aRowL;
            int ch = kc * 2 + aChunkOff;
            ldsm4(aH[kc][g], sb + OFF_QH + arow * 128 + (uint32_t)((ch ^ (arow & 7)) << 4));
        }

    float C2[2][8][4];
    #pragma unroll
    for (int g = 0; g < 2; g++)
        #pragma unroll
        for (int t = 0; t < 8; t++)
            #pragma unroll
            for (int k = 0; k < 4; k++) C2[g][t][k] = 0.0f;

    for (int p = 0; p < NPAIRS; p++) {
        // pair p's two tiles were prefetched in iteration p-1 (or prologue)
        CP_WAIT0();
        __syncthreads();   // pair data visible; pair p-1 buffers free

        // prefetch pair p+1 into the buffers pair p-1 used
        if (p + 1 < NPAIRS) {
            #pragma unroll
            for (int t = 0; t < 2; t++) {
                int kt = 2 * (p + 1) + t;
                const unsigned char* src = kvb + (size_t)kt * BUFSTR;
                uint32_t dst = sb + BUF0 + (uint32_t)(kt & 3) * BUFSTR;
                #pragma unroll
                for (int it = 0; it < 8; it++) {
                    int off = (tid + it * NT) * 16;
                    cp16(dst + off, src + off);
                }
                CP_COMMIT();
            }
        }

        // ---- process both tiles of the pair, no barrier in between ----
        #pragma unroll
        for (int half = 0; half < 2; half++) {
            const int kt = 2 * p + half;
            const uint32_t cbuf = sb + BUF0 + (uint32_t)(kt & 3) * BUFSTR;

            // gemm1: C1 = Qh Kh^T over warp's 32 rows x 64 cols
            float C1[2][8][4];
            #pragma unroll
            for (int g = 0; g < 2; g++)
                #pragma unroll
                for (int t = 0; t < 8; t++)
                    #pragma unroll
                    for (int k = 0; k < 4; k++) C1[g][t][k] = 0.0f;

            #pragma unroll
            for (int kc = 0; kc < 4; kc++) {
                #pragma unroll
                for (int nt2 = 0; nt2 < 4; nt2++) {
                    int brow = wn * 64 + nt2 * 16 + bRowOff;
                    int bch  = kc * 2 + bChunkOff;
                    uint32_t bHf[4];
                    ldsm4(bHf, cbuf + brow * 128 + (uint32_t)((bch ^ (brow & 7)) << 4));
                    #pragma unroll
                    for (int g = 0; g < 2; g++) {
                        mmah(C1[g][2 * nt2],     aH[kc][g], bHf[0], bHf[1]);
                        mmah(C1[g][2 * nt2 + 1], aH[kc][g], bHf[2], bHf[3]);
                    }
                }
            }

            // fused epilogue + gemm2 (Ph only), one 16-k-col chunk at a time
            const uint32_t vbase = cbuf + 16384;
            #pragma unroll
            for (int nt2 = 0; nt2 < 4; nt2++) {
                uint32_t ah[2][4];
                #pragma unroll
                for (int g = 0; g < 2; g++) {
                    float* ag = attng
                        + (size_t)(wq * 32 + g * 16 + (lane >> 2)) * S_LEN
                        + (size_t)kt * BLK + wn * 64 + nt2 * 16 + (lane & 3) * 2;
                    #pragma unroll
                    for (int sub = 0; sub < 2; sub++) {
                        float* c = C1[g][2 * nt2 + sub];
                        float p0 = fmaxf(c[0], 0.0f);
                        float p1 = fmaxf(c[1], 0.0f);
                        float p2 = fmaxf(c[2], 0.0f);
                        float p3 = fmaxf(c[3], 0.0f);
                        __stcs((float2*)(ag + sub * 8),             make_float2(p0, p1));
                        __stcs((float2*)(ag + sub * 8 + 8 * S_LEN), make_float2(p2, p3));
                        ah[g][2 * sub]     = packh(p0, p1);
                        ah[g][2 * sub + 1] = packh(p2, p3);
                    }
                }
                int vrow = wn * 64 + nt2 * 16 + vRowOff;
                #pragma unroll
                for (int ntV = 0; ntV < 4; ntV++) {
                    int vch = ntV * 2 + vChunkOff;
                    uint32_t vf[4];
                    ldsm4t(vf, vbase + vrow * 128 + (uint32_t)((vch ^ (vrow & 7)) << 4));
                    #pragma unroll
                    for (int g = 0; g < 2; g++) {
                        mmah(C2[g][2 * ntV],     ah[g], vf[0], vf[1]);
                        mmah(C2[g][2 * ntV + 1], ah[g], vf[2], vf[3]);
                    }
                }
            }
        }
    }

    // ---- split-k reduction of C2 across wn pairs, then write ctx ----
    __syncthreads();            // all warps done with tile buffers
    float* red = (float*)smc;   // overlays Q + tile buffers
    if (wn == 1) {
        #pragma unroll
        for (int g = 0; g < 2; g++) {
            int r = wq * 32 + g * 16 + (lane >> 2);
            #pragma unroll
            for (int t = 0; t < 8; t++) {
                int col = (t >> 1) * 16 + (t & 1) * 8 + (lane & 3) * 2;
                *(float2*)&red[(size_t)r * RED_STRIDE + col] =
                    make_float2(C2[g][t][0], C2[g][t][1]);
                *(float2*)&red[(size_t)(r + 8) * RED_STRIDE + col] =
                    make_float2(C2[g][t][2], C2[g][t][3]);
            }
        }
    }
    __syncthreads();
    if (wn == 0) {
        #pragma unroll
        for (int g = 0; g < 2; g++) {
            int r = wq * 32 + g * 16 + (lane >> 2);
            #pragma unroll
            for (int t = 0; t < 8; t++) {
                int col = (t >> 1) * 16 + (t & 1) * 8 + (lane & 3) * 2;
                float2 p0 = *(float2*)&red[(size_t)r * RED_STRIDE + col];
                float2 p1 = *(float2*)&red[(size_t)(r + 8) * RED_STRIDE + col];
                *(float2*)&ctxg[(size_t)r * HDIM + col] =
                    make_float2(C2[g][t][0] + p0.x, C2[g][t][1] + p0.y);
                *(float2*)&ctxg[(size_t)(r + 8) * HDIM + col] =
                    make_float2(C2[g][t][2] + p1.x, C2[g][t][3] + p1.y);
            }
        }
    }
}

extern "C" void kernel_launch(void* const* d_in, const int* in_sizes, int n_in,
                              void* d_out, int out_size) {
    const float* Q = (const float*)d_in[0];
    const float* K = (const float*)d_in[1];
    const float* V = (const float*)d_in[2];
    float* ctx  = (float*)d_out;
    float* attn = (float*)d_out + CTX_ELEMS;

    dim3 pg(NTILES, NBH);
    conv_kv_kernel<<<pg, NT>>>(K, V);

    cudaFuncSetAttribute(relu_attn_pipe4_kernel,
                         cudaFuncAttributeMaxDynamicSharedMemorySize, SMEM_BYTES);
    dim3 grid(S_LEN / BLK, NBH);
    relu_attn_pipe4_kernel<<<grid, NT, SMEM_BYTES>>>(Q, ctx, attn);
}